// round 2
// baseline (speedup 1.0000x reference)
#include <cuda_runtime.h>
#include <math.h>

#define SVAL 64
#define DIM 256

__device__ __forceinline__ float sel4(float4 q, int o) {
    float a = (o & 2) ? q.z : q.x;
    float b = (o & 2) ? q.w : q.y;
    return (o & 1) ? b : a;
}

__global__ __launch_bounds__(256, 4) void psf_sample_kernel(
    const float* __restrict__ vol,        // [256,256,256] (z,y,x)
    const float* __restrict__ sampleGrid, // [N,3]
    const float* __restrict__ ax,         // [N,6]
    const float* __restrict__ bound,      // [N,2,3]
    const float* __restrict__ invcov,     // [3,3]
    const float* __restrict__ xyz_psf,    // [N,S,3]
    float* __restrict__ out,              // [N]
    int N)
{
    const int warps_per_block = blockDim.x >> 5;
    const int n = blockIdx.x * warps_per_block + (threadIdx.x >> 5);
    if (n >= N) return;
    const int lane = threadIdx.x & 31;

    // ---- per-ray uniform setup (broadcast loads, redundant per lane) ----
    const float vx = __ldg(ax + (size_t)n * 6 + 0);
    const float vy = __ldg(ax + (size_t)n * 6 + 1);
    const float vz = __ldg(ax + (size_t)n * 6 + 2);
    const float tx = __ldg(ax + (size_t)n * 6 + 3);
    const float ty = __ldg(ax + (size_t)n * 6 + 4);
    const float tz = __ldg(ax + (size_t)n * 6 + 5);

    const float theta = sqrtf(vx * vx + vy * vy + vz * vz);
    const float invt = 1.0f / fmaxf(theta, 1e-12f);
    const float kx = vx * invt, ky = vy * invt, kz = vz * invt;
    const float st = sinf(theta);
    const float ct = cosf(theta);
    const float oc = 1.0f - ct;

    const float r00 = 1.0f - oc * (ky * ky + kz * kz);
    const float r01 = -st * kz + oc * kx * ky;
    const float r02 =  st * ky + oc * kx * kz;
    const float r10 =  st * kz + oc * kx * ky;
    const float r11 = 1.0f - oc * (kx * kx + kz * kz);
    const float r12 = -st * kx + oc * ky * kz;
    const float r20 = -st * ky + oc * kx * kz;
    const float r21 =  st * kx + oc * ky * kz;
    const float r22 = 1.0f - oc * (kx * kx + ky * ky);

    const float sgx = __ldg(sampleGrid + (size_t)n * 3 + 0);
    const float sgy = __ldg(sampleGrid + (size_t)n * 3 + 1);
    const float sgz = __ldg(sampleGrid + (size_t)n * 3 + 2);

    const float px = sgx + tx, py = sgy + ty, pz = sgz + tz;
    const float cx = r00 * px + r01 * py + r02 * pz;
    const float cy = r10 * px + r11 * py + r12 * pz;
    const float cz = r20 * px + r21 * py + r22 * pz;

    const float hx = 0.5f * (__ldg(bound + (size_t)n * 6 + 3) - __ldg(bound + (size_t)n * 6 + 0));
    const float hy = 0.5f * (__ldg(bound + (size_t)n * 6 + 4) - __ldg(bound + (size_t)n * 6 + 1));
    const float hz = 0.5f * (__ldg(bound + (size_t)n * 6 + 5) - __ldg(bound + (size_t)n * 6 + 2));

    const float c00 = __ldg(invcov + 0), c01 = __ldg(invcov + 1), c02 = __ldg(invcov + 2);
    const float c10 = __ldg(invcov + 3), c11 = __ldg(invcov + 4), c12 = __ldg(invcov + 5);
    const float c20 = __ldg(invcov + 6), c21 = __ldg(invcov + 7), c22 = __ldg(invcov + 8);

    float sum_vw = 0.0f;
    float sum_w = 0.0f;

    const float* psf_base = xyz_psf + (size_t)n * SVAL * 3;

    // pix = world * (256/255) - 0.5   (algebraic fold of the grid-normalize + unnormalize)
    const float SCL = 256.0f / 255.0f;

#pragma unroll
    for (int rep = 0; rep < 2; rep++) {
        const int s = lane + rep * 32;
        const float ex = __ldg(psf_base + s * 3 + 0) * hx;
        const float ey = __ldg(psf_base + s * 3 + 1) * hy;
        const float ez = __ldg(psf_base + s * 3 + 2) * hz;

        const float pixx = fmaf(cx + ex, SCL, -0.5f);
        const float pixy = fmaf(cy + ey, SCL, -0.5f);
        const float pixz = fmaf(cz + ez, SCL, -0.5f);

        const float fx0 = floorf(pixx), fy0 = floorf(pixy), fz0 = floorf(pixz);
        const int x0 = (int)fx0, y0 = (int)fy0, z0 = (int)fz0;
        const float fx = pixx - fx0, fy = pixy - fy0, fz = pixz - fz0;

        const bool vx0 = (x0 >= 0) & (x0 < DIM);
        const bool vx1 = (x0 >= -1) & (x0 < DIM - 1);
        const bool vy0 = (y0 >= 0) & (y0 < DIM);
        const bool vy1 = (y0 >= -1) & (y0 < DIM - 1);
        const bool vz0 = (z0 >= 0) & (z0 < DIM);
        const bool vz1 = (z0 >= -1) & (z0 < DIM - 1);

        // x-pair served by one 16B-aligned float4 per row (+ rare fixup when o==3)
        const int xi0 = min(max(x0, 0), DIM - 1);
        const int xi1 = min(max(x0 + 1, 0), DIM - 1);
        const int e  = xi0 & ~3;
        const int o  = xi0 & 3;
        const int o1 = xi1 - e;               // 0..4
        const bool extra = (o1 == 4);

        const int yc0 = min(max(y0, 0), DIM - 1);
        const int yc1 = min(max(y0 + 1, 0), DIM - 1);
        const int zc0 = min(max(z0, 0), DIM - 1);
        const int zc1 = min(max(z0 + 1, 0), DIM - 1);

        const bool rv00 = vz0 & vy0;
        const bool rv01 = vz0 & vy1;
        const bool rv10 = vz1 & vy0;
        const bool rv11 = vz1 & vy1;

        const int b00 = (zc0 * DIM + yc0) * DIM + e;
        const int b01 = (zc0 * DIM + yc1) * DIM + e;
        const int b10 = (zc1 * DIM + yc0) * DIM + e;
        const int b11 = (zc1 * DIM + yc1) * DIM + e;

        const float4 Z4 = make_float4(0.f, 0.f, 0.f, 0.f);
        const float4 q00 = rv00 ? __ldg((const float4*)(vol + b00)) : Z4;
        const float4 q01 = rv01 ? __ldg((const float4*)(vol + b01)) : Z4;
        const float4 q10 = rv10 ? __ldg((const float4*)(vol + b10)) : Z4;
        const float4 q11 = rv11 ? __ldg((const float4*)(vol + b11)) : Z4;

        const float s00 = (extra & rv00) ? __ldg(vol + b00 + 4) : 0.f;
        const float s01 = (extra & rv01) ? __ldg(vol + b01 + 4) : 0.f;
        const float s10 = (extra & rv10) ? __ldg(vol + b10 + 4) : 0.f;
        const float s11 = (extra & rv11) ? __ldg(vol + b11 + 4) : 0.f;

        const int o1s = extra ? 0 : o1;       // safe selector when extra path taken

        const float v000 = vx0 ? sel4(q00, o)  : 0.f;
        const float v001 = vx1 ? (extra ? s00 : sel4(q00, o1s)) : 0.f;
        const float v010 = vx0 ? sel4(q01, o)  : 0.f;
        const float v011 = vx1 ? (extra ? s01 : sel4(q01, o1s)) : 0.f;
        const float v100 = vx0 ? sel4(q10, o)  : 0.f;
        const float v101 = vx1 ? (extra ? s10 : sel4(q10, o1s)) : 0.f;
        const float v110 = vx0 ? sel4(q11, o)  : 0.f;
        const float v111 = vx1 ? (extra ? s11 : sel4(q11, o1s)) : 0.f;

        const float wx0 = 1.0f - fx, wy0 = 1.0f - fy, wz0 = 1.0f - fz;

        const float vz0p =
            wy0 * fmaf(wx0, v000, fx * v001) + fy * fmaf(wx0, v010, fx * v011);
        const float vz1p =
            wy0 * fmaf(wx0, v100, fx * v101) + fy * fmaf(wx0, v110, fx * v111);
        const float val = fmaf(wz0, vz0p, fz * vz1p);

        const float q =
            ex * (c00 * ex + c01 * ey + c02 * ez) +
            ey * (c10 * ex + c11 * ey + c12 * ez) +
            ez * (c20 * ex + c21 * ey + c22 * ez);
        const float w = __expf(-0.5f * q);

        sum_vw = fmaf(w, val, sum_vw);
        sum_w += w;
    }

#pragma unroll
    for (int off = 16; off > 0; off >>= 1) {
        sum_vw += __shfl_xor_sync(0xFFFFFFFFu, sum_vw, off);
        sum_w  += __shfl_xor_sync(0xFFFFFFFFu, sum_w, off);
    }

    if (lane == 0) {
        out[n] = sum_vw / sum_w;
    }
}

extern "C" void kernel_launch(void* const* d_in, const int* in_sizes, int n_in,
                              void* d_out, int out_size)
{
    const float* x          = (const float*)d_in[0];
    const float* sampleGrid = (const float*)d_in[1];
    const float* ax         = (const float*)d_in[2];
    const float* bound      = (const float*)d_in[3];
    const float* invcov     = (const float*)d_in[4];
    const float* xyz_psf    = (const float*)d_in[5];
    float* out = (float*)d_out;

    const int N = in_sizes[1] / 3;

    const int threads = 256;
    const int warps_per_block = threads / 32;
    const int blocks = (N + warps_per_block - 1) / warps_per_block;
    psf_sample_kernel<<<blocks, threads>>>(x, sampleGrid, ax, bound, invcov,
                                           xyz_psf, out, N);
}

// round 3
// speedup vs baseline: 1.4757x; 1.4757x over previous
#include <cuda_runtime.h>
#include <cuda_fp16.h>
#include <math.h>

#define SVAL 64
#define DIM 256
#define VOXELS (DIM * DIM * DIM)

// Scratch: pair-duplicated half-precision volume. dup[i] = (vol[i], vol[i+1 within row]).
__device__ __half2 g_dup[VOXELS];

__global__ __launch_bounds__(256) void build_dup_kernel(const float* __restrict__ vol)
{
    const int t = blockIdx.x * blockDim.x + threadIdx.x; // one thread per 4 voxels
    if (t >= VOXELS / 4) return;
    const int base = t * 4;
    const float4 v = __ldg((const float4*)(vol + base));
    const int x = base & (DIM - 1);
    // neighbor of v.w; at row end (x==252) the hi of dup[255] is unused (masked), reuse v.w
    const float nxt = (x == DIM - 4) ? v.w : __ldg(vol + base + 4);

    __half2 h0 = __floats2half2_rn(v.x, v.y);
    __half2 h1 = __floats2half2_rn(v.y, v.z);
    __half2 h2 = __floats2half2_rn(v.z, v.w);
    __half2 h3 = __floats2half2_rn(v.w, nxt);

    uint4 p;
    p.x = *(unsigned int*)&h0;
    p.y = *(unsigned int*)&h1;
    p.z = *(unsigned int*)&h2;
    p.w = *(unsigned int*)&h3;
    ((uint4*)g_dup)[t] = p;
}

__global__ __launch_bounds__(256) void psf_sample_kernel(
    const float* __restrict__ sampleGrid, // [N,3]
    const float* __restrict__ ax,         // [N,6]
    const float* __restrict__ bound,      // [N,2,3]
    const float* __restrict__ invcov,     // [3,3]
    const float* __restrict__ xyz_psf,    // [N,S,3]
    float* __restrict__ out,              // [N]
    int N)
{
    const int warps_per_block = blockDim.x >> 5;
    const int n = blockIdx.x * warps_per_block + (threadIdx.x >> 5);
    if (n >= N) return;
    const int lane = threadIdx.x & 31;

    // ---- per-ray uniform setup (broadcast loads, redundant per lane) ----
    const float vx = __ldg(ax + (size_t)n * 6 + 0);
    const float vy = __ldg(ax + (size_t)n * 6 + 1);
    const float vz = __ldg(ax + (size_t)n * 6 + 2);
    const float tx = __ldg(ax + (size_t)n * 6 + 3);
    const float ty = __ldg(ax + (size_t)n * 6 + 4);
    const float tz = __ldg(ax + (size_t)n * 6 + 5);

    const float theta = sqrtf(vx * vx + vy * vy + vz * vz);
    const float invt = 1.0f / fmaxf(theta, 1e-12f);
    const float kx = vx * invt, ky = vy * invt, kz = vz * invt;
    const float st = sinf(theta);
    const float ct = cosf(theta);
    const float oc = 1.0f - ct;

    const float r00 = 1.0f - oc * (ky * ky + kz * kz);
    const float r01 = -st * kz + oc * kx * ky;
    const float r02 =  st * ky + oc * kx * kz;
    const float r10 =  st * kz + oc * kx * ky;
    const float r11 = 1.0f - oc * (kx * kx + kz * kz);
    const float r12 = -st * kx + oc * ky * kz;
    const float r20 = -st * ky + oc * kx * kz;
    const float r21 =  st * kx + oc * ky * kz;
    const float r22 = 1.0f - oc * (kx * kx + ky * ky);

    const float sgx = __ldg(sampleGrid + (size_t)n * 3 + 0);
    const float sgy = __ldg(sampleGrid + (size_t)n * 3 + 1);
    const float sgz = __ldg(sampleGrid + (size_t)n * 3 + 2);

    const float px = sgx + tx, py = sgy + ty, pz = sgz + tz;
    const float cx = r00 * px + r01 * py + r02 * pz;
    const float cy = r10 * px + r11 * py + r12 * pz;
    const float cz = r20 * px + r21 * py + r22 * pz;

    const float hx = 0.5f * (__ldg(bound + (size_t)n * 6 + 3) - __ldg(bound + (size_t)n * 6 + 0));
    const float hy = 0.5f * (__ldg(bound + (size_t)n * 6 + 4) - __ldg(bound + (size_t)n * 6 + 1));
    const float hz = 0.5f * (__ldg(bound + (size_t)n * 6 + 5) - __ldg(bound + (size_t)n * 6 + 2));

    const float c00 = __ldg(invcov + 0), c01 = __ldg(invcov + 1), c02 = __ldg(invcov + 2);
    const float c10 = __ldg(invcov + 3), c11 = __ldg(invcov + 4), c12 = __ldg(invcov + 5);
    const float c20 = __ldg(invcov + 6), c21 = __ldg(invcov + 7), c22 = __ldg(invcov + 8);

    float sum_vw = 0.0f;
    float sum_w = 0.0f;

    const float* psf_base = xyz_psf + (size_t)n * SVAL * 3;

    // pix = world * (256/255) - 0.5
    const float SCL = 256.0f / 255.0f;

#pragma unroll
    for (int rep = 0; rep < 2; rep++) {
        const int s = lane + rep * 32;
        const float ex = __ldg(psf_base + s * 3 + 0) * hx;
        const float ey = __ldg(psf_base + s * 3 + 1) * hy;
        const float ez = __ldg(psf_base + s * 3 + 2) * hz;

        const float pixx = fmaf(cx + ex, SCL, -0.5f);
        const float pixy = fmaf(cy + ey, SCL, -0.5f);
        const float pixz = fmaf(cz + ez, SCL, -0.5f);

        const float fx0 = floorf(pixx), fy0 = floorf(pixy), fz0 = floorf(pixz);
        const int x0 = (int)fx0, y0 = (int)fy0, z0 = (int)fz0;
        const float fx = pixx - fx0, fy = pixy - fy0, fz = pixz - fz0;

        const bool vx0 = (x0 >= 0) & (x0 < DIM);
        const bool vx1 = (x0 >= -1) & (x0 < DIM - 1);
        const bool vy0 = (y0 >= 0) & (y0 < DIM);
        const bool vy1 = (y0 >= -1) & (y0 < DIM - 1);
        const bool vz0 = (z0 >= 0) & (z0 < DIM);
        const bool vz1 = (z0 >= -1) & (z0 < DIM - 1);

        const int xc0 = min(max(x0, 0), DIM - 1);
        const int yc0 = min(max(y0, 0), DIM - 1);
        const int yc1 = min(max(y0 + 1, 0), DIM - 1);
        const int zc0 = min(max(z0, 0), DIM - 1);
        const int zc1 = min(max(z0 + 1, 0), DIM - 1);

        const bool rv00 = vz0 & vy0;
        const bool rv01 = vz0 & vy1;
        const bool rv10 = vz1 & vy0;
        const bool rv11 = vz1 & vy1;

        const int b00 = (zc0 * DIM + yc0) * DIM + xc0;
        const int b01 = (zc0 * DIM + yc1) * DIM + xc0;
        const int b10 = (zc1 * DIM + yc0) * DIM + xc0;
        const int b11 = (zc1 * DIM + yc1) * DIM + xc0;

        const __half2 HZ = __float2half2_rn(0.0f);
        const __half2 d00 = rv00 ? __ldg(g_dup + b00) : HZ;
        const __half2 d01 = rv01 ? __ldg(g_dup + b01) : HZ;
        const __half2 d10 = rv10 ? __ldg(g_dup + b10) : HZ;
        const __half2 d11 = rv11 ? __ldg(g_dup + b11) : HZ;

        const float2 f00 = __half22float2(d00);
        const float2 f01 = __half22float2(d01);
        const float2 f10 = __half22float2(d10);
        const float2 f11 = __half22float2(d11);

        const bool xin = (x0 >= 0);   // if x0==-1, the clamped load's .x IS vol[0] == v1

        const float v000 = vx0 ? f00.x : 0.f;
        const float v001 = vx1 ? (xin ? f00.y : f00.x) : 0.f;
        const float v010 = vx0 ? f01.x : 0.f;
        const float v011 = vx1 ? (xin ? f01.y : f01.x) : 0.f;
        const float v100 = vx0 ? f10.x : 0.f;
        const float v101 = vx1 ? (xin ? f10.y : f10.x) : 0.f;
        const float v110 = vx0 ? f11.x : 0.f;
        const float v111 = vx1 ? (xin ? f11.y : f11.x) : 0.f;

        const float wx0 = 1.0f - fx, wy0 = 1.0f - fy, wz0 = 1.0f - fz;

        const float vz0p =
            wy0 * fmaf(wx0, v000, fx * v001) + fy * fmaf(wx0, v010, fx * v011);
        const float vz1p =
            wy0 * fmaf(wx0, v100, fx * v101) + fy * fmaf(wx0, v110, fx * v111);
        const float val = fmaf(wz0, vz0p, fz * vz1p);

        const float q =
            ex * (c00 * ex + c01 * ey + c02 * ez) +
            ey * (c10 * ex + c11 * ey + c12 * ez) +
            ez * (c20 * ex + c21 * ey + c22 * ez);
        const float w = __expf(-0.5f * q);

        sum_vw = fmaf(w, val, sum_vw);
        sum_w += w;
    }

#pragma unroll
    for (int off = 16; off > 0; off >>= 1) {
        sum_vw += __shfl_xor_sync(0xFFFFFFFFu, sum_vw, off);
        sum_w  += __shfl_xor_sync(0xFFFFFFFFu, sum_w, off);
    }

    if (lane == 0) {
        out[n] = sum_vw / sum_w;
    }
}

extern "C" void kernel_launch(void* const* d_in, const int* in_sizes, int n_in,
                              void* d_out, int out_size)
{
    const float* x          = (const float*)d_in[0];
    const float* sampleGrid = (const float*)d_in[1];
    const float* ax         = (const float*)d_in[2];
    const float* bound      = (const float*)d_in[3];
    const float* invcov     = (const float*)d_in[4];
    const float* xyz_psf    = (const float*)d_in[5];
    float* out = (float*)d_out;

    const int N = in_sizes[1] / 3;

    // Pre-pass: build pair-duplicated half2 volume
    {
        const int threads = 256;
        const int work = VOXELS / 4;
        const int blocks = (work + threads - 1) / threads;
        build_dup_kernel<<<blocks, threads>>>(x);
    }

    // Main kernel: warp per ray
    {
        const int threads = 256;
        const int warps_per_block = threads / 32;
        const int blocks = (N + warps_per_block - 1) / warps_per_block;
        psf_sample_kernel<<<blocks, threads>>>(sampleGrid, ax, bound, invcov,
                                               xyz_psf, out, N);
    }
}